// round 9
// baseline (speedup 1.0000x reference)
#include <cuda_runtime.h>
#include <cuda_bf16.h>
#include <stdint.h>

#define TT 2048
#define DD 64
#define HH 16
#define BB 2

__device__ float g_m[BB*HH*TT];
__device__ float g_inv[BB*HH*TT];

// warp-level bf16 tensor-core mma: D(16x8,f32) += A(16x16,bf16) * B(16x8,bf16)
__device__ __forceinline__ void mma16816(float4& d, const uint32_t* a,
                                         uint32_t b0, uint32_t b1) {
    asm volatile("mma.sync.aligned.m16n8k16.row.col.f32.bf16.bf16.f32 "
        "{%0,%1,%2,%3}, {%4,%5,%6,%7}, {%8,%9}, {%0,%1,%2,%3};"
        : "+f"(d.x), "+f"(d.y), "+f"(d.z), "+f"(d.w)
        : "r"(a[0]), "r"(a[1]), "r"(a[2]), "r"(a[3]), "r"(b0), "r"(b1));
}
// split (x,y) fp32 pair -> bf16x2 hi (x in low half) + bf16x2 lo residual
__device__ __forceinline__ void cvt_hilo2(float x, float y, uint32_t& hi, uint32_t& lo) {
    __nv_bfloat162 hb = __floats2bfloat162_rn(x, y);
    __nv_bfloat162 lb = __floats2bfloat162_rn(x - __bfloat162float(hb.x),
                                              y - __bfloat162float(hb.y));
    hi = *reinterpret_cast<uint32_t*>(&hb);
    lo = *reinterpret_cast<uint32_t*>(&lb);
}

// ==================== Kernel A: QK^T (HMMA bf16x3) ====================
// raw scores -> gattn; per-row (m, 1/sum) -> g_m/g_inv
#define A_KHI 0            // K tile hi: 128 keys x 72 bf16 (64 + 8 pad) = 18432 B
#define A_KLO 18432
#define A_MASK 36864       // 2048 ints = 8192 B
#define A_TOTAL 45056

__global__ __launch_bounds__(256, 2)
void qk_mma(const float* __restrict__ gq, const float* __restrict__ gk,
            const int* __restrict__ gmask, const float* __restrict__ gbias,
            float* __restrict__ gattn)
{
    extern __shared__ char sm[];
    char* s_khi = sm + A_KHI;
    char* s_klo = sm + A_KLO;
    int*  s_mask = (int*)(sm + A_MASK);

    const int t = threadIdx.x, wid = t >> 5, lane = t & 31;
    const int h = blockIdx.y, b = blockIdx.z;
    const int q0 = blockIdx.x * 128;
    const int g = lane >> 2, qd = lane & 3;
    const int lr = wid*16 + g;                     // local q rows lr, lr+8

    const float* qb = gq + (((size_t)(b*HH + h))*TT + q0)*DD;
    const float* kb = gk + ((size_t)(b*HH + h))*TT*DD;
    const float* bbp = gbias + ((size_t)h*TT + q0)*TT;
    float*       ab = gattn + (((size_t)(b*HH + h))*TT + q0)*TT;

    // mask -> smem (512 int4)
    ((int4*)s_mask)[t*2]   = ((const int4*)(gmask + b*TT))[t*2];
    ((int4*)s_mask)[t*2+1] = ((const int4*)(gmask + b*TT))[t*2+1];

    // Q A-fragments (x0.125 folded in; exactly representable), bf16 hi/lo
    uint32_t ah[4][4], al[4][4];
    {
        const float* r0p = qb + (size_t)lr*DD;
        const float* r1p = qb + (size_t)(lr+8)*DD;
        #pragma unroll
        for (int ks = 0; ks < 4; ++ks) {
            const int c0 = ks*16 + qd*2;
            float2 x00 = *(const float2*)(r0p + c0);
            float2 x02 = *(const float2*)(r0p + c0 + 8);
            float2 x10 = *(const float2*)(r1p + c0);
            float2 x12 = *(const float2*)(r1p + c0 + 8);
            cvt_hilo2(x00.x*0.125f, x00.y*0.125f, ah[ks][0], al[ks][0]);
            cvt_hilo2(x10.x*0.125f, x10.y*0.125f, ah[ks][1], al[ks][1]);
            cvt_hilo2(x02.x*0.125f, x02.y*0.125f, ah[ks][2], al[ks][2]);
            cvt_hilo2(x12.x*0.125f, x12.y*0.125f, ah[ks][3], al[ks][3]);
        }
    }

    float m0 = -3.4e38f, s0 = 0.f, m1 = -3.4e38f, s1 = 0.f;

    for (int j = 0; j < 16; ++j) {
        __syncthreads();
        {   // stage K tile: row=key (144B stride), d contiguous as bf16 pairs
            const int key = t >> 1, half = t & 1;
            const float* src = kb + (size_t)(j*128 + key)*DD + half*32;
            #pragma unroll
            for (int ch = 0; ch < 4; ++ch) {
                float4 a = ((const float4*)src)[ch*2];
                float4 c = ((const float4*)src)[ch*2+1];
                uint32_t h0,l0,h1,l1,h2,l2,h3,l3;
                cvt_hilo2(a.x,a.y,h0,l0); cvt_hilo2(a.z,a.w,h1,l1);
                cvt_hilo2(c.x,c.y,h2,l2); cvt_hilo2(c.z,c.w,h3,l3);
                const int off = key*144 + half*64 + ch*16;
                *(uint4*)(s_khi + off) = make_uint4(h0,h1,h2,h3);
                *(uint4*)(s_klo + off) = make_uint4(l0,l1,l2,l3);
            }
        }
        __syncthreads();

        #pragma unroll 2
        for (int n = 0; n < 16; ++n) {
            float4 d = make_float4(0.f, 0.f, 0.f, 0.f);
            const int keyl = n*8 + g;
            const char* bhp = s_khi + keyl*144 + qd*4;
            const char* blp = s_klo + keyl*144 + qd*4;
            #pragma unroll
            for (int ks = 0; ks < 4; ++ks) {
                uint32_t bh0 = *(const uint32_t*)(bhp + ks*32);
                uint32_t bh1 = *(const uint32_t*)(bhp + ks*32 + 16);
                uint32_t bl0 = *(const uint32_t*)(blp + ks*32);
                uint32_t bl1 = *(const uint32_t*)(blp + ks*32 + 16);
                mma16816(d, ah[ks], bh0, bh1);
                mma16816(d, al[ks], bh0, bh1);
                mma16816(d, ah[ks], bl0, bl1);
            }
            const int c = j*128 + n*8 + qd*2;
            int2   mv  = *(const int2*)&s_mask[c];
            float2 bi0 = *(const float2*)(bbp + (size_t)lr*TT + c);
            float2 bi1 = *(const float2*)(bbp + (size_t)(lr+8)*TT + c);
            float v00 = mv.x ? d.x + bi0.x : -1e9f;
            float v01 = mv.y ? d.y + bi0.y : -1e9f;
            float v10 = mv.x ? d.z + bi1.x : -1e9f;
            float v11 = mv.y ? d.w + bi1.y : -1e9f;
            *(float2*)(ab + (size_t)lr*TT + c)     = make_float2(v00, v01);
            *(float2*)(ab + (size_t)(lr+8)*TT + c) = make_float2(v10, v11);
            float nm0 = fmaxf(m0, fmaxf(v00, v01));
            s0 = s0*__expf(m0 - nm0) + __expf(v00 - nm0) + __expf(v01 - nm0);
            m0 = nm0;
            float nm1 = fmaxf(m1, fmaxf(v10, v11));
            s1 = s1*__expf(m1 - nm1) + __expf(v10 - nm1) + __expf(v11 - nm1);
            m1 = nm1;
        }
    }

    // reduce (m,s) across the 4 quad lanes that share each row
    #pragma unroll
    for (int o = 1; o < 4; o <<= 1) {
        float mo = __shfl_xor_sync(0xffffffffu, m0, o);
        float so = __shfl_xor_sync(0xffffffffu, s0, o);
        float nm = fmaxf(m0, mo);
        s0 = s0*__expf(m0 - nm) + so*__expf(mo - nm); m0 = nm;
        mo = __shfl_xor_sync(0xffffffffu, m1, o);
        so = __shfl_xor_sync(0xffffffffu, s1, o);
        nm = fmaxf(m1, mo);
        s1 = s1*__expf(m1 - nm) + so*__expf(mo - nm); m1 = nm;
    }
    if (qd == 0) {
        const size_t gi = (size_t)(b*HH + h)*TT + q0;
        g_m[gi + lr]       = m0;  g_inv[gi + lr]     = 1.f/s0;
        g_m[gi + lr + 8]   = m1;  g_inv[gi + lr + 8] = 1.f/s1;
    }
}

// ==================== Kernel B: PV (HMMA bf16x3) ====================
// normalize raw scores -> final attn (in place); O = P @ V
#define B_VHI 0            // V^T hi: 64 d-rows x 136 bf16 (128 keys + 8 pad) = 17408 B
#define B_VLO 17408
#define B_TOTAL 34816

__global__ __launch_bounds__(256, 2)
void pv_mma(const float* __restrict__ gv, float* __restrict__ gattn,
            float* __restrict__ gout)
{
    extern __shared__ char sm[];
    char* s_vhi = sm + B_VHI;
    char* s_vlo = sm + B_VLO;

    const int t = threadIdx.x, wid = t >> 5, lane = t & 31;
    const int h = blockIdx.y, b = blockIdx.z;
    const int q0 = blockIdx.x * 128;
    const int g = lane >> 2, qd = lane & 3;
    const int lr = wid*16 + g;

    const float* vb = gv + ((size_t)(b*HH + h))*TT*DD;
    float*       ab = gattn + (((size_t)(b*HH + h))*TT + q0)*TT;

    const size_t st = (size_t)(b*HH + h)*TT + q0;
    const float m_0 = g_m[st + lr],     i_0 = g_inv[st + lr];
    const float m_1 = g_m[st + lr + 8], i_1 = g_inv[st + lr + 8];

    float4 o[8];
    #pragma unroll
    for (int i = 0; i < 8; ++i) o[i] = make_float4(0.f, 0.f, 0.f, 0.f);

    for (int j = 0; j < 16; ++j) {
        __syncthreads();
        // stage V^T: row d (64), cols = key-pairs (bf16x2 of keys 2kp,2kp+1), 272B stride
        #pragma unroll
        for (int it = 0; it < 4; ++it) {
            const int item = t + it*256;
            const int kp = item & 63, dq = item >> 6;   // kp 0..63, dq 0..15
            const float* v0 = vb + (size_t)(j*128 + 2*kp)*DD + dq*4;
            float4 a = *(const float4*)v0;
            float4 c = *(const float4*)(v0 + DD);
            #pragma unroll
            for (int u = 0; u < 4; ++u) {
                float x = (u==0)?a.x:(u==1)?a.y:(u==2)?a.z:a.w;
                float y = (u==0)?c.x:(u==1)?c.y:(u==2)?c.z:c.w;
                uint32_t hp, lp;
                cvt_hilo2(x, y, hp, lp);
                const int off = (dq*4 + u)*272 + kp*4;
                *(uint32_t*)(s_vhi + off) = hp;
                *(uint32_t*)(s_vlo + off) = lp;
            }
        }
        __syncthreads();

        #pragma unroll 2
        for (int kst = 0; kst < 8; ++kst) {
            // A-fragments: raw -> exp-normalize -> write final attn + bf16 hi/lo
            const int kc = j*128 + kst*16 + qd*2;
            float* p00 = ab + (size_t)lr*TT + kc;
            float* p10 = ab + (size_t)(lr+8)*TT + kc;
            float2 x00 = *(const float2*)p00;
            float2 x02 = *(const float2*)(p00 + 8);
            float2 x10 = *(const float2*)p10;
            float2 x12 = *(const float2*)(p10 + 8);
            x00.x = __expf(x00.x - m_0)*i_0;  x00.y = __expf(x00.y - m_0)*i_0;
            x02.x = __expf(x02.x - m_0)*i_0;  x02.y = __expf(x02.y - m_0)*i_0;
            x10.x = __expf(x10.x - m_1)*i_1;  x10.y = __expf(x10.y - m_1)*i_1;
            x12.x = __expf(x12.x - m_1)*i_1;  x12.y = __expf(x12.y - m_1)*i_1;
            *(float2*)p00       = x00;  *(float2*)(p00 + 8) = x02;
            *(float2*)p10       = x10;  *(float2*)(p10 + 8) = x12;
            uint32_t ph[4], pl[4];
            cvt_hilo2(x00.x, x00.y, ph[0], pl[0]);
            cvt_hilo2(x10.x, x10.y, ph[1], pl[1]);
            cvt_hilo2(x02.x, x02.y, ph[2], pl[2]);
            cvt_hilo2(x12.x, x12.y, ph[3], pl[3]);

            const char* bhp = s_vhi + g*272 + kst*32 + qd*4;
            const char* blp = s_vlo + g*272 + kst*32 + qd*4;
            #pragma unroll
            for (int ns = 0; ns < 8; ++ns) {
                uint32_t bh0 = *(const uint32_t*)(bhp + ns*2176);
                uint32_t bh1 = *(const uint32_t*)(bhp + ns*2176 + 16);
                uint32_t bl0 = *(const uint32_t*)(blp + ns*2176);
                uint32_t bl1 = *(const uint32_t*)(blp + ns*2176 + 16);
                mma16816(o[ns], ph, bh0, bh1);
                mma16816(o[ns], pl, bh0, bh1);
                mma16816(o[ns], ph, bl0, bl1);
            }
        }
    }

    float* ob = gout + (((size_t)(b*HH + h))*TT + q0)*DD;
    #pragma unroll
    for (int ns = 0; ns < 8; ++ns) {
        const int c = ns*8 + qd*2;
        *(float2*)(ob + (size_t)lr*DD + c)     = make_float2(o[ns].x, o[ns].y);
        *(float2*)(ob + (size_t)(lr+8)*DD + c) = make_float2(o[ns].z, o[ns].w);
    }
}

extern "C" void kernel_launch(void* const* d_in, const int* in_sizes, int n_in,
                              void* d_out, int out_size)
{
    const float* q    = (const float*)d_in[0];
    const float* k    = (const float*)d_in[1];
    const float* v    = (const float*)d_in[2];
    const int*   mask = (const int*)d_in[3];
    const float* bias = (const float*)d_in[4];
    float* out  = (float*)d_out;
    float* attn = out + (long long)BB*HH*TT*DD;

    cudaFuncSetAttribute(qk_mma, cudaFuncAttributeMaxDynamicSharedMemorySize, A_TOTAL);
    cudaFuncSetAttribute(pv_mma, cudaFuncAttributeMaxDynamicSharedMemorySize, B_TOTAL);

    dim3 grid(TT/128, HH, BB);
    qk_mma<<<grid, 256, A_TOTAL>>>(q, k, mask, bias, attn);
    pv_mma<<<grid, 256, B_TOTAL>>>(v, attn, out);
}

// round 10
// speedup vs baseline: 1.6042x; 1.6042x over previous
#include <cuda_runtime.h>
#include <cuda_bf16.h>
#include <stdint.h>

#define TT 2048
#define DD 64
#define HH 16
#define BB 2

__device__ float g_m[BB*HH*TT];
__device__ float g_inv[BB*HH*TT];

__device__ __forceinline__ void mma16816(float4& d, const uint32_t* a,
                                         uint32_t b0, uint32_t b1) {
    asm volatile("mma.sync.aligned.m16n8k16.row.col.f32.bf16.bf16.f32 "
        "{%0,%1,%2,%3}, {%4,%5,%6,%7}, {%8,%9}, {%0,%1,%2,%3};"
        : "+f"(d.x), "+f"(d.y), "+f"(d.z), "+f"(d.w)
        : "r"(a[0]), "r"(a[1]), "r"(a[2]), "r"(a[3]), "r"(b0), "r"(b1));
}
__device__ __forceinline__ void cvt_hilo2(float x, float y, uint32_t& hi, uint32_t& lo) {
    __nv_bfloat162 hb = __floats2bfloat162_rn(x, y);
    __nv_bfloat162 lb = __floats2bfloat162_rn(x - __bfloat162float(hb.x),
                                              y - __bfloat162float(hb.y));
    hi = *reinterpret_cast<uint32_t*>(&hb);
    lo = *reinterpret_cast<uint32_t*>(&lb);
}

// ==================== Kernel A: QK^T (HMMA bf16x3) — unchanged, passing ====================
#define A_KHI 0
#define A_KLO 18432
#define A_MASK 36864
#define A_TOTAL 45056

__global__ __launch_bounds__(256, 2)
void qk_mma(const float* __restrict__ gq, const float* __restrict__ gk,
            const int* __restrict__ gmask, const float* __restrict__ gbias,
            float* __restrict__ gattn)
{
    extern __shared__ char sm[];
    char* s_khi = sm + A_KHI;
    char* s_klo = sm + A_KLO;
    int*  s_mask = (int*)(sm + A_MASK);

    const int t = threadIdx.x, wid = t >> 5, lane = t & 31;
    const int h = blockIdx.y, b = blockIdx.z;
    const int q0 = blockIdx.x * 128;
    const int g = lane >> 2, qd = lane & 3;
    const int lr = wid*16 + g;

    const float* qb = gq + (((size_t)(b*HH + h))*TT + q0)*DD;
    const float* kb = gk + ((size_t)(b*HH + h))*TT*DD;
    const float* bbp = gbias + ((size_t)h*TT + q0)*TT;
    float*       ab = gattn + (((size_t)(b*HH + h))*TT + q0)*TT;

    ((int4*)s_mask)[t*2]   = ((const int4*)(gmask + b*TT))[t*2];
    ((int4*)s_mask)[t*2+1] = ((const int4*)(gmask + b*TT))[t*2+1];

    uint32_t ah[4][4], al[4][4];
    {
        const float* r0p = qb + (size_t)lr*DD;
        const float* r1p = qb + (size_t)(lr+8)*DD;
        #pragma unroll
        for (int ks = 0; ks < 4; ++ks) {
            const int c0 = ks*16 + qd*2;
            float2 x00 = *(const float2*)(r0p + c0);
            float2 x02 = *(const float2*)(r0p + c0 + 8);
            float2 x10 = *(const float2*)(r1p + c0);
            float2 x12 = *(const float2*)(r1p + c0 + 8);
            cvt_hilo2(x00.x*0.125f, x00.y*0.125f, ah[ks][0], al[ks][0]);
            cvt_hilo2(x10.x*0.125f, x10.y*0.125f, ah[ks][1], al[ks][1]);
            cvt_hilo2(x02.x*0.125f, x02.y*0.125f, ah[ks][2], al[ks][2]);
            cvt_hilo2(x12.x*0.125f, x12.y*0.125f, ah[ks][3], al[ks][3]);
        }
    }

    float m0 = -3.4e38f, s0 = 0.f, m1 = -3.4e38f, s1 = 0.f;

    for (int j = 0; j < 16; ++j) {
        __syncthreads();
        {
            const int key = t >> 1, half = t & 1;
            const float* src = kb + (size_t)(j*128 + key)*DD + half*32;
            #pragma unroll
            for (int ch = 0; ch < 4; ++ch) {
                float4 a = ((const float4*)src)[ch*2];
                float4 c = ((const float4*)src)[ch*2+1];
                uint32_t h0,l0,h1,l1,h2,l2,h3,l3;
                cvt_hilo2(a.x,a.y,h0,l0); cvt_hilo2(a.z,a.w,h1,l1);
                cvt_hilo2(c.x,c.y,h2,l2); cvt_hilo2(c.z,c.w,h3,l3);
                const int off = key*144 + half*64 + ch*16;
                *(uint4*)(s_khi + off) = make_uint4(h0,h1,h2,h3);
                *(uint4*)(s_klo + off) = make_uint4(l0,l1,l2,l3);
            }
        }
        __syncthreads();

        #pragma unroll 2
        for (int n = 0; n < 16; ++n) {
            float4 d = make_float4(0.f, 0.f, 0.f, 0.f);
            const int keyl = n*8 + g;
            const char* bhp = s_khi + keyl*144 + qd*4;
            const char* blp = s_klo + keyl*144 + qd*4;
            #pragma unroll
            for (int ks = 0; ks < 4; ++ks) {
                uint32_t bh0 = *(const uint32_t*)(bhp + ks*32);
                uint32_t bh1 = *(const uint32_t*)(bhp + ks*32 + 16);
                uint32_t bl0 = *(const uint32_t*)(blp + ks*32);
                uint32_t bl1 = *(const uint32_t*)(blp + ks*32 + 16);
                mma16816(d, ah[ks], bh0, bh1);
                mma16816(d, al[ks], bh0, bh1);
                mma16816(d, ah[ks], bl0, bl1);
            }
            const int c = j*128 + n*8 + qd*2;
            int2   mv  = *(const int2*)&s_mask[c];
            float2 bi0 = *(const float2*)(bbp + (size_t)lr*TT + c);
            float2 bi1 = *(const float2*)(bbp + (size_t)(lr+8)*TT + c);
            float v00 = mv.x ? d.x + bi0.x : -1e9f;
            float v01 = mv.y ? d.y + bi0.y : -1e9f;
            float v10 = mv.x ? d.z + bi1.x : -1e9f;
            float v11 = mv.y ? d.w + bi1.y : -1e9f;
            *(float2*)(ab + (size_t)lr*TT + c)     = make_float2(v00, v01);
            *(float2*)(ab + (size_t)(lr+8)*TT + c) = make_float2(v10, v11);
            float nm0 = fmaxf(m0, fmaxf(v00, v01));
            s0 = s0*__expf(m0 - nm0) + __expf(v00 - nm0) + __expf(v01 - nm0);
            m0 = nm0;
            float nm1 = fmaxf(m1, fmaxf(v10, v11));
            s1 = s1*__expf(m1 - nm1) + __expf(v10 - nm1) + __expf(v11 - nm1);
            m1 = nm1;
        }
    }

    #pragma unroll
    for (int o = 1; o < 4; o <<= 1) {
        float mo = __shfl_xor_sync(0xffffffffu, m0, o);
        float so = __shfl_xor_sync(0xffffffffu, s0, o);
        float nm = fmaxf(m0, mo);
        s0 = s0*__expf(m0 - nm) + so*__expf(mo - nm); m0 = nm;
        mo = __shfl_xor_sync(0xffffffffu, m1, o);
        so = __shfl_xor_sync(0xffffffffu, s1, o);
        nm = fmaxf(m1, mo);
        s1 = s1*__expf(m1 - nm) + so*__expf(mo - nm); m1 = nm;
    }
    if (qd == 0) {
        const size_t gi = (size_t)(b*HH + h)*TT + q0;
        g_m[gi + lr]       = m0;  g_inv[gi + lr]     = 1.f/s0;
        g_m[gi + lr + 8]   = m1;  g_inv[gi + lr + 8] = 1.f/s1;
    }
}

// ==================== Kernel B: PV (HMMA bf16x3) — smem-staged P ====================
// per 64-key tile: bulk normalize (coalesced gmem r/w) -> P hi/lo smem; V^T hi/lo smem; MMA from smem
#define PST 144            // P smem row stride bytes (64 cols bf16 + 16 pad)
#define VSTB 144           // V^T smem row stride bytes (32 key-pairs*4B + 16 pad)
#define B_PHI 0            // 128 rows * 144
#define B_PLO 18432
#define B_VHI 36864        // 64 rows * 144
#define B_VLO 46080
#define B_TOTAL 55296

__global__ __launch_bounds__(256, 2)
void pv_mma(const float* __restrict__ gv, float* __restrict__ gattn,
            float* __restrict__ gout)
{
    extern __shared__ char sm[];
    char* s_phi = sm + B_PHI;
    char* s_plo = sm + B_PLO;
    char* s_vhi = sm + B_VHI;
    char* s_vlo = sm + B_VLO;

    const int t = threadIdx.x, wid = t >> 5, lane = t & 31;
    const int h = blockIdx.y, b = blockIdx.z;
    const int q0 = blockIdx.x * 128;
    const int g = lane >> 2, qd = lane & 3;
    const int lr = wid*16 + g;

    const float* vb = gv + ((size_t)(b*HH + h))*TT*DD;
    float*       ab = gattn + (((size_t)(b*HH + h))*TT + q0)*TT;
    const size_t st = (size_t)(b*HH + h)*TT + q0;

    // staging row for P: thread owns row srow, 32-col half shalf (one full 128B line)
    const int srow = t >> 1, shalf = t & 1;
    const float stm = g_m[st + srow];
    const float sti = g_inv[st + srow];

    // V staging: kp = lane (key pair), dq = warp id (d-octet) -- dq warp-uniform
    const int vkp = lane, vdq = wid;

    float4 o[8];
    #pragma unroll
    for (int i = 0; i < 8; ++i) o[i] = make_float4(0.f, 0.f, 0.f, 0.f);

    for (int j = 0; j < 32; ++j) {
        __syncthreads();   // previous MMA reads done before smem overwrite
        // ---- stage P: coalesced read raw, batch expf, write final attn, hi/lo -> smem ----
        {
            float* graw = ab + (size_t)srow*TT + j*64 + shalf*32;
            float4 x[8];
            #pragma unroll
            for (int ch = 0; ch < 8; ++ch) x[ch] = ((const float4*)graw)[ch];
            #pragma unroll
            for (int ch = 0; ch < 8; ++ch) {
                x[ch].x = __expf(x[ch].x - stm)*sti;
                x[ch].y = __expf(x[ch].y - stm)*sti;
                x[ch].z = __expf(x[ch].z - stm)*sti;
                x[ch].w = __expf(x[ch].w - stm)*sti;
            }
            #pragma unroll
            for (int ch = 0; ch < 8; ++ch) ((float4*)graw)[ch] = x[ch];
            #pragma unroll
            for (int ch = 0; ch < 4; ++ch) {
                uint32_t h0,l0,h1,l1,h2,l2,h3,l3;
                cvt_hilo2(x[2*ch].x,   x[2*ch].y,   h0, l0);
                cvt_hilo2(x[2*ch].z,   x[2*ch].w,   h1, l1);
                cvt_hilo2(x[2*ch+1].x, x[2*ch+1].y, h2, l2);
                cvt_hilo2(x[2*ch+1].z, x[2*ch+1].w, h3, l3);
                const int off = srow*PST + shalf*64 + ch*16;
                *(uint4*)(s_phi + off) = make_uint4(h0,h1,h2,h3);
                *(uint4*)(s_plo + off) = make_uint4(l0,l1,l2,l3);
            }
        }
        // ---- stage V^T hi/lo: rows d (64), cols key-pairs; conflict-free STS.32 ----
        {
            const float* v0 = vb + (size_t)(j*64 + 2*vkp)*DD + vdq*8;
            float4 a0 = *(const float4*)v0;
            float4 a1 = *(const float4*)(v0 + 4);
            float4 c0 = *(const float4*)(v0 + DD);
            float4 c1 = *(const float4*)(v0 + DD + 4);
            #pragma unroll
            for (int u = 0; u < 4; ++u) {
                float x = (u==0)?a0.x:(u==1)?a0.y:(u==2)?a0.z:a0.w;
                float y = (u==0)?c0.x:(u==1)?c0.y:(u==2)?c0.z:c0.w;
                uint32_t hp, lp;
                cvt_hilo2(x, y, hp, lp);
                const int off = (vdq*8 + u)*VSTB + vkp*4;
                *(uint32_t*)(s_vhi + off) = hp;
                *(uint32_t*)(s_vlo + off) = lp;
            }
            #pragma unroll
            for (int u = 0; u < 4; ++u) {
                float x = (u==0)?a1.x:(u==1)?a1.y:(u==2)?a1.z:a1.w;
                float y = (u==0)?c1.x:(u==1)?c1.y:(u==2)?c1.z:c1.w;
                uint32_t hp, lp;
                cvt_hilo2(x, y, hp, lp);
                const int off = (vdq*8 + 4 + u)*VSTB + vkp*4;
                *(uint32_t*)(s_vhi + off) = hp;
                *(uint32_t*)(s_vlo + off) = lp;
            }
        }
        __syncthreads();

        // ---- MMA from smem ----
        #pragma unroll
        for (int kst = 0; kst < 4; ++kst) {
            const int abase = lr*PST + kst*32 + qd*4;
            uint32_t ph[4], pl[4];
            ph[0] = *(const uint32_t*)(s_phi + abase);
            ph[1] = *(const uint32_t*)(s_phi + abase + 8*PST);
            ph[2] = *(const uint32_t*)(s_phi + abase + 16);
            ph[3] = *(const uint32_t*)(s_phi + abase + 8*PST + 16);
            pl[0] = *(const uint32_t*)(s_plo + abase);
            pl[1] = *(const uint32_t*)(s_plo + abase + 8*PST);
            pl[2] = *(const uint32_t*)(s_plo + abase + 16);
            pl[3] = *(const uint32_t*)(s_plo + abase + 8*PST + 16);
            #pragma unroll
            for (int ns = 0; ns < 8; ++ns) {
                const int bbase = (ns*8 + g)*VSTB + kst*32 + qd*4;
                uint32_t bh0 = *(const uint32_t*)(s_vhi + bbase);
                uint32_t bh1 = *(const uint32_t*)(s_vhi + bbase + 16);
                uint32_t bl0 = *(const uint32_t*)(s_vlo + bbase);
                uint32_t bl1 = *(const uint32_t*)(s_vlo + bbase + 16);
                mma16816(o[ns], ph, bh0, bh1);
                mma16816(o[ns], pl, bh0, bh1);
                mma16816(o[ns], ph, bl0, bl1);
            }
        }
    }

    float* ob = gout + (((size_t)(b*HH + h))*TT + q0)*DD;
    #pragma unroll
    for (int ns = 0; ns < 8; ++ns) {
        const int c = ns*8 + qd*2;
        *(float2*)(ob + (size_t)lr*DD + c)     = make_float2(o[ns].x, o[ns].y);
        *(float2*)(ob + (size_t)(lr+8)*DD + c) = make_float2(o[ns].z, o[ns].w);
    }
}

extern "C" void kernel_launch(void* const* d_in, const int* in_sizes, int n_in,
                              void* d_out, int out_size)
{
    const float* q    = (const float*)d_in[0];
    const float* k    = (const float*)d_in[1];
    const float* v    = (const float*)d_in[2];
    const int*   mask = (const int*)d_in[3];
    const float* bias = (const float*)d_in[4];
    float* out  = (float*)d_out;
    float* attn = out + (long long)BB*HH*TT*DD;

    cudaFuncSetAttribute(qk_mma, cudaFuncAttributeMaxDynamicSharedMemorySize, A_TOTAL);
    cudaFuncSetAttribute(pv_mma, cudaFuncAttributeMaxDynamicSharedMemorySize, B_TOTAL);

    dim3 grid(TT/128, HH, BB);
    qk_mma<<<grid, 256, A_TOTAL>>>(q, k, mask, bias, attn);
    pv_mma<<<grid, 256, B_TOTAL>>>(v, attn, out);
}

// round 11
// speedup vs baseline: 1.7148x; 1.0690x over previous
#include <cuda_runtime.h>
#include <cuda_bf16.h>
#include <stdint.h>

#define TT 2048
#define DD 64
#define HH 16
#define BB 2

__device__ float g_m[BB*HH*TT];
__device__ float g_inv[BB*HH*TT];

__device__ __forceinline__ void mma16816(float4& d, const uint32_t* a,
                                         uint32_t b0, uint32_t b1) {
    asm volatile("mma.sync.aligned.m16n8k16.row.col.f32.bf16.bf16.f32 "
        "{%0,%1,%2,%3}, {%4,%5,%6,%7}, {%8,%9}, {%0,%1,%2,%3};"
        : "+f"(d.x), "+f"(d.y), "+f"(d.z), "+f"(d.w)
        : "r"(a[0]), "r"(a[1]), "r"(a[2]), "r"(a[3]), "r"(b0), "r"(b1));
}
__device__ __forceinline__ void cvt_hilo2(float x, float y, uint32_t& hi, uint32_t& lo) {
    __nv_bfloat162 hb = __floats2bfloat162_rn(x, y);
    __nv_bfloat162 lb = __floats2bfloat162_rn(x - __bfloat162float(hb.x),
                                              y - __bfloat162float(hb.y));
    hi = *reinterpret_cast<uint32_t*>(&hb);
    lo = *reinterpret_cast<uint32_t*>(&lb);
}

// ==================== Kernel A: QK^T (HMMA bf16x3) — unchanged, passing ====================
#define A_KHI 0
#define A_KLO 18432
#define A_MASK 36864
#define A_TOTAL 45056

__global__ __launch_bounds__(256, 2)
void qk_mma(const float* __restrict__ gq, const float* __restrict__ gk,
            const int* __restrict__ gmask, const float* __restrict__ gbias,
            float* __restrict__ gattn)
{
    extern __shared__ char sm[];
    char* s_khi = sm + A_KHI;
    char* s_klo = sm + A_KLO;
    int*  s_mask = (int*)(sm + A_MASK);

    const int t = threadIdx.x, wid = t >> 5, lane = t & 31;
    const int h = blockIdx.y, b = blockIdx.z;
    const int q0 = blockIdx.x * 128;
    const int g = lane >> 2, qd = lane & 3;
    const int lr = wid*16 + g;

    const float* qb = gq + (((size_t)(b*HH + h))*TT + q0)*DD;
    const float* kb = gk + ((size_t)(b*HH + h))*TT*DD;
    const float* bbp = gbias + ((size_t)h*TT + q0)*TT;
    float*       ab = gattn + (((size_t)(b*HH + h))*TT + q0)*TT;

    ((int4*)s_mask)[t*2]   = ((const int4*)(gmask + b*TT))[t*2];
    ((int4*)s_mask)[t*2+1] = ((const int4*)(gmask + b*TT))[t*2+1];

    uint32_t ah[4][4], al[4][4];
    {
        const float* r0p = qb + (size_t)lr*DD;
        const float* r1p = qb + (size_t)(lr+8)*DD;
        #pragma unroll
        for (int ks = 0; ks < 4; ++ks) {
            const int c0 = ks*16 + qd*2;
            float2 x00 = *(const float2*)(r0p + c0);
            float2 x02 = *(const float2*)(r0p + c0 + 8);
            float2 x10 = *(const float2*)(r1p + c0);
            float2 x12 = *(const float2*)(r1p + c0 + 8);
            cvt_hilo2(x00.x*0.125f, x00.y*0.125f, ah[ks][0], al[ks][0]);
            cvt_hilo2(x10.x*0.125f, x10.y*0.125f, ah[ks][1], al[ks][1]);
            cvt_hilo2(x02.x*0.125f, x02.y*0.125f, ah[ks][2], al[ks][2]);
            cvt_hilo2(x12.x*0.125f, x12.y*0.125f, ah[ks][3], al[ks][3]);
        }
    }

    float m0 = -3.4e38f, s0 = 0.f, m1 = -3.4e38f, s1 = 0.f;

    for (int j = 0; j < 16; ++j) {
        __syncthreads();
        {
            const int key = t >> 1, half = t & 1;
            const float* src = kb + (size_t)(j*128 + key)*DD + half*32;
            #pragma unroll
            for (int ch = 0; ch < 4; ++ch) {
                float4 a = ((const float4*)src)[ch*2];
                float4 c = ((const float4*)src)[ch*2+1];
                uint32_t h0,l0,h1,l1,h2,l2,h3,l3;
                cvt_hilo2(a.x,a.y,h0,l0); cvt_hilo2(a.z,a.w,h1,l1);
                cvt_hilo2(c.x,c.y,h2,l2); cvt_hilo2(c.z,c.w,h3,l3);
                const int off = key*144 + half*64 + ch*16;
                *(uint4*)(s_khi + off) = make_uint4(h0,h1,h2,h3);
                *(uint4*)(s_klo + off) = make_uint4(l0,l1,l2,l3);
            }
        }
        __syncthreads();

        #pragma unroll 2
        for (int n = 0; n < 16; ++n) {
            float4 d = make_float4(0.f, 0.f, 0.f, 0.f);
            const int keyl = n*8 + g;
            const char* bhp = s_khi + keyl*144 + qd*4;
            const char* blp = s_klo + keyl*144 + qd*4;
            #pragma unroll
            for (int ks = 0; ks < 4; ++ks) {
                uint32_t bh0 = *(const uint32_t*)(bhp + ks*32);
                uint32_t bh1 = *(const uint32_t*)(bhp + ks*32 + 16);
                uint32_t bl0 = *(const uint32_t*)(blp + ks*32);
                uint32_t bl1 = *(const uint32_t*)(blp + ks*32 + 16);
                mma16816(d, ah[ks], bh0, bh1);
                mma16816(d, al[ks], bh0, bh1);
                mma16816(d, ah[ks], bl0, bl1);
            }
            const int c = j*128 + n*8 + qd*2;
            int2   mv  = *(const int2*)&s_mask[c];
            float2 bi0 = *(const float2*)(bbp + (size_t)lr*TT + c);
            float2 bi1 = *(const float2*)(bbp + (size_t)(lr+8)*TT + c);
            float v00 = mv.x ? d.x + bi0.x : -1e9f;
            float v01 = mv.y ? d.y + bi0.y : -1e9f;
            float v10 = mv.x ? d.z + bi1.x : -1e9f;
            float v11 = mv.y ? d.w + bi1.y : -1e9f;
            *(float2*)(ab + (size_t)lr*TT + c)     = make_float2(v00, v01);
            *(float2*)(ab + (size_t)(lr+8)*TT + c) = make_float2(v10, v11);
            float nm0 = fmaxf(m0, fmaxf(v00, v01));
            s0 = s0*__expf(m0 - nm0) + __expf(v00 - nm0) + __expf(v01 - nm0);
            m0 = nm0;
            float nm1 = fmaxf(m1, fmaxf(v10, v11));
            s1 = s1*__expf(m1 - nm1) + __expf(v10 - nm1) + __expf(v11 - nm1);
            m1 = nm1;
        }
    }

    #pragma unroll
    for (int o = 1; o < 4; o <<= 1) {
        float mo = __shfl_xor_sync(0xffffffffu, m0, o);
        float so = __shfl_xor_sync(0xffffffffu, s0, o);
        float nm = fmaxf(m0, mo);
        s0 = s0*__expf(m0 - nm) + so*__expf(mo - nm); m0 = nm;
        mo = __shfl_xor_sync(0xffffffffu, m1, o);
        so = __shfl_xor_sync(0xffffffffu, s1, o);
        nm = fmaxf(m1, mo);
        s1 = s1*__expf(m1 - nm) + so*__expf(mo - nm); m1 = nm;
    }
    if (qd == 0) {
        const size_t gi = (size_t)(b*HH + h)*TT + q0;
        g_m[gi + lr]       = m0;  g_inv[gi + lr]     = 1.f/s0;
        g_m[gi + lr + 8]   = m1;  g_inv[gi + lr + 8] = 1.f/s1;
    }
}

// ==================== Kernel B: PV (HMMA bf16x3) — coalesced P staging ====================
#define PST 144
#define VSTB 144
#define B_PHI 0
#define B_PLO 18432
#define B_VHI 36864
#define B_VLO 46080
#define B_STAT 55296       // float2[128] softmax stats
#define B_TOTAL 56320

__global__ __launch_bounds__(256, 2)
void pv_mma(const float* __restrict__ gv, float* __restrict__ gattn,
            float* __restrict__ gout)
{
    extern __shared__ char sm[];
    char* s_phi = sm + B_PHI;
    char* s_plo = sm + B_PLO;
    char* s_vhi = sm + B_VHI;
    char* s_vlo = sm + B_VLO;
    float2* s_stat = (float2*)(sm + B_STAT);

    const int t = threadIdx.x, wid = t >> 5, lane = t & 31;
    const int h = blockIdx.y, b = blockIdx.z;
    const int q0 = blockIdx.x * 128;
    const int g = lane >> 2, qd = lane & 3;
    const int lr = wid*16 + g;

    const float* vb = gv + ((size_t)(b*HH + h))*TT*DD;
    float*       ab = gattn + (((size_t)(b*HH + h))*TT + q0)*TT;
    const size_t st = (size_t)(b*HH + h)*TT + q0;

    // cache softmax stats in smem
    if (t < 128) s_stat[t] = make_float2(g_m[st + t], g_inv[st + t]);

    // P staging map: warp covers rows wid*16..+15; lanes 0-15 = one row (float4 cols),
    // lane bit4 selects row of the pair -> every LDG/STG instruction is 4-wavefront coalesced
    const int hl = lane >> 4;          // row parity within pair
    const int lc = (lane & 15) * 4;    // float4 column

    // V staging: kp = lane (key pair), dq = wid (d-octet)
    const int vkp = lane, vdq = wid;

    float4 o[8];
    #pragma unroll
    for (int i = 0; i < 8; ++i) o[i] = make_float4(0.f, 0.f, 0.f, 0.f);

    for (int j = 0; j < 32; ++j) {
        __syncthreads();   // prior MMA reads done; stats visible (j=0)
        // ---- stage P: coalesced read raw -> exp-normalize -> coalesced write attn + smem hi/lo ----
        #pragma unroll
        for (int rp = 0; rp < 8; ++rp) {
            const int r = wid*16 + rp*2 + hl;
            const float2 ms = s_stat[r];
            float* graw = ab + (size_t)r*TT + j*64 + lc;
            float4 x = *(const float4*)graw;
            x.x = __expf(x.x - ms.x)*ms.y;
            x.y = __expf(x.y - ms.x)*ms.y;
            x.z = __expf(x.z - ms.x)*ms.y;
            x.w = __expf(x.w - ms.x)*ms.y;
            *(float4*)graw = x;
            uint32_t h0,l0,h1,l1;
            cvt_hilo2(x.x, x.y, h0, l0);
            cvt_hilo2(x.z, x.w, h1, l1);
            const int off = r*PST + lc*2;
            *(uint2*)(s_phi + off) = make_uint2(h0, h1);
            *(uint2*)(s_plo + off) = make_uint2(l0, l1);
        }
        // ---- stage V^T hi/lo (at byte floor already) ----
        {
            const float* v0 = vb + (size_t)(j*64 + 2*vkp)*DD + vdq*8;
            float4 a0 = *(const float4*)v0;
            float4 a1 = *(const float4*)(v0 + 4);
            float4 c0 = *(const float4*)(v0 + DD);
            float4 c1 = *(const float4*)(v0 + DD + 4);
            #pragma unroll
            for (int u = 0; u < 4; ++u) {
                float x = (u==0)?a0.x:(u==1)?a0.y:(u==2)?a0.z:a0.w;
                float y = (u==0)?c0.x:(u==1)?c0.y:(u==2)?c0.z:c0.w;
                uint32_t hp, lp;
                cvt_hilo2(x, y, hp, lp);
                const int off = (vdq*8 + u)*VSTB + vkp*4;
                *(uint32_t*)(s_vhi + off) = hp;
                *(uint32_t*)(s_vlo + off) = lp;
            }
            #pragma unroll
            for (int u = 0; u < 4; ++u) {
                float x = (u==0)?a1.x:(u==1)?a1.y:(u==2)?a1.z:a1.w;
                float y = (u==0)?c1.x:(u==1)?c1.y:(u==2)?c1.z:c1.w;
                uint32_t hp, lp;
                cvt_hilo2(x, y, hp, lp);
                const int off = (vdq*8 + 4 + u)*VSTB + vkp*4;
                *(uint32_t*)(s_vhi + off) = hp;
                *(uint32_t*)(s_vlo + off) = lp;
            }
        }
        __syncthreads();

        // ---- MMA from smem ----
        #pragma unroll
        for (int kst = 0; kst < 4; ++kst) {
            const int abase = lr*PST + kst*32 + qd*4;
            uint32_t ph[4], pl[4];
            ph[0] = *(const uint32_t*)(s_phi + abase);
            ph[1] = *(const uint32_t*)(s_phi + abase + 8*PST);
            ph[2] = *(const uint32_t*)(s_phi + abase + 16);
            ph[3] = *(const uint32_t*)(s_phi + abase + 8*PST + 16);
            pl[0] = *(const uint32_t*)(s_plo + abase);
            pl[1] = *(const uint32_t*)(s_plo + abase + 8*PST);
            pl[2] = *(const uint32_t*)(s_plo + abase + 16);
            pl[3] = *(const uint32_t*)(s_plo + abase + 8*PST + 16);
            #pragma unroll
            for (int ns = 0; ns < 8; ++ns) {
                const int bbase = (ns*8 + g)*VSTB + kst*32 + qd*4;
                uint32_t bh0 = *(const uint32_t*)(s_vhi + bbase);
                uint32_t bh1 = *(const uint32_t*)(s_vhi + bbase + 16);
                uint32_t bl0 = *(const uint32_t*)(s_vlo + bbase);
                uint32_t bl1 = *(const uint32_t*)(s_vlo + bbase + 16);
                mma16816(o[ns], ph, bh0, bh1);
                mma16816(o[ns], pl, bh0, bh1);
                mma16816(o[ns], ph, bl0, bl1);
            }
        }
    }

    float* ob = gout + (((size_t)(b*HH + h))*TT + q0)*DD;
    #pragma unroll
    for (int ns = 0; ns < 8; ++ns) {
        const int c = ns*8 + qd*2;
        *(float2*)(ob + (size_t)lr*DD + c)     = make_float2(o[ns].x, o[ns].y);
        *(float2*)(ob + (size_t)(lr+8)*DD + c) = make_float2(o[ns].z, o[ns].w);
    }
}

extern "C" void kernel_launch(void* const* d_in, const int* in_sizes, int n_in,
                              void* d_out, int out_size)
{
    const float* q    = (const float*)d_in[0];
    const float* k    = (const float*)d_in[1];
    const float* v    = (const float*)d_in[2];
    const int*   mask = (const int*)d_in[3];
    const float* bias = (const float*)d_in[4];
    float* out  = (float*)d_out;
    float* attn = out + (long long)BB*HH*TT*DD;

    cudaFuncSetAttribute(qk_mma, cudaFuncAttributeMaxDynamicSharedMemorySize, A_TOTAL);
    cudaFuncSetAttribute(pv_mma, cudaFuncAttributeMaxDynamicSharedMemorySize, B_TOTAL);

    dim3 grid(TT/128, HH, BB);
    qk_mma<<<grid, 256, A_TOTAL>>>(q, k, mask, bias, attn);
    pv_mma<<<grid, 256, B_TOTAL>>>(v, attn, out);
}

// round 12
// speedup vs baseline: 2.1423x; 1.2493x over previous
#include <cuda_runtime.h>
#include <cuda_bf16.h>
#include <stdint.h>

#define TT 2048
#define DD 64
#define HH 16
#define BB 2

__device__ float g_m[BB*HH*TT];
__device__ float g_inv[BB*HH*TT];

__device__ __forceinline__ void mma16816(float4& d, const uint32_t* a,
                                         uint32_t b0, uint32_t b1) {
    asm volatile("mma.sync.aligned.m16n8k16.row.col.f32.bf16.bf16.f32 "
        "{%0,%1,%2,%3}, {%4,%5,%6,%7}, {%8,%9}, {%0,%1,%2,%3};"
        : "+f"(d.x), "+f"(d.y), "+f"(d.z), "+f"(d.w)
        : "r"(a[0]), "r"(a[1]), "r"(a[2]), "r"(a[3]), "r"(b0), "r"(b1));
}
__device__ __forceinline__ void cvt_hilo2(float x, float y, uint32_t& hi, uint32_t& lo) {
    __nv_bfloat162 hb = __floats2bfloat162_rn(x, y);
    __nv_bfloat162 lb = __floats2bfloat162_rn(x - __bfloat162float(hb.x),
                                              y - __bfloat162float(hb.y));
    hi = *reinterpret_cast<uint32_t*>(&hb);
    lo = *reinterpret_cast<uint32_t*>(&lb);
}

// ==================== Kernel A: QK^T (HMMA bf16x3) — unchanged, passing ====================
#define A_KHI 0
#define A_KLO 18432
#define A_MASK 36864
#define A_TOTAL 45056

__global__ __launch_bounds__(256, 2)
void qk_mma(const float* __restrict__ gq, const float* __restrict__ gk,
            const int* __restrict__ gmask, const float* __restrict__ gbias,
            float* __restrict__ gattn)
{
    extern __shared__ char sm[];
    char* s_khi = sm + A_KHI;
    char* s_klo = sm + A_KLO;
    int*  s_mask = (int*)(sm + A_MASK);

    const int t = threadIdx.x, wid = t >> 5, lane = t & 31;
    const int h = blockIdx.y, b = blockIdx.z;
    const int q0 = blockIdx.x * 128;
    const int g = lane >> 2, qd = lane & 3;
    const int lr = wid*16 + g;

    const float* qb = gq + (((size_t)(b*HH + h))*TT + q0)*DD;
    const float* kb = gk + ((size_t)(b*HH + h))*TT*DD;
    const float* bbp = gbias + ((size_t)h*TT + q0)*TT;
    float*       ab = gattn + (((size_t)(b*HH + h))*TT + q0)*TT;

    ((int4*)s_mask)[t*2]   = ((const int4*)(gmask + b*TT))[t*2];
    ((int4*)s_mask)[t*2+1] = ((const int4*)(gmask + b*TT))[t*2+1];

    uint32_t ah[4][4], al[4][4];
    {
        const float* r0p = qb + (size_t)lr*DD;
        const float* r1p = qb + (size_t)(lr+8)*DD;
        #pragma unroll
        for (int ks = 0; ks < 4; ++ks) {
            const int c0 = ks*16 + qd*2;
            float2 x00 = *(const float2*)(r0p + c0);
            float2 x02 = *(const float2*)(r0p + c0 + 8);
            float2 x10 = *(const float2*)(r1p + c0);
            float2 x12 = *(const float2*)(r1p + c0 + 8);
            cvt_hilo2(x00.x*0.125f, x00.y*0.125f, ah[ks][0], al[ks][0]);
            cvt_hilo2(x10.x*0.125f, x10.y*0.125f, ah[ks][1], al[ks][1]);
            cvt_hilo2(x02.x*0.125f, x02.y*0.125f, ah[ks][2], al[ks][2]);
            cvt_hilo2(x12.x*0.125f, x12.y*0.125f, ah[ks][3], al[ks][3]);
        }
    }

    float m0 = -3.4e38f, s0 = 0.f, m1 = -3.4e38f, s1 = 0.f;

    for (int j = 0; j < 16; ++j) {
        __syncthreads();
        {
            const int key = t >> 1, half = t & 1;
            const float* src = kb + (size_t)(j*128 + key)*DD + half*32;
            #pragma unroll
            for (int ch = 0; ch < 4; ++ch) {
                float4 a = ((const float4*)src)[ch*2];
                float4 c = ((const float4*)src)[ch*2+1];
                uint32_t h0,l0,h1,l1,h2,l2,h3,l3;
                cvt_hilo2(a.x,a.y,h0,l0); cvt_hilo2(a.z,a.w,h1,l1);
                cvt_hilo2(c.x,c.y,h2,l2); cvt_hilo2(c.z,c.w,h3,l3);
                const int off = key*144 + half*64 + ch*16;
                *(uint4*)(s_khi + off) = make_uint4(h0,h1,h2,h3);
                *(uint4*)(s_klo + off) = make_uint4(l0,l1,l2,l3);
            }
        }
        __syncthreads();

        #pragma unroll 2
        for (int n = 0; n < 16; ++n) {
            float4 d = make_float4(0.f, 0.f, 0.f, 0.f);
            const int keyl = n*8 + g;
            const char* bhp = s_khi + keyl*144 + qd*4;
            const char* blp = s_klo + keyl*144 + qd*4;
            #pragma unroll
            for (int ks = 0; ks < 4; ++ks) {
                uint32_t bh0 = *(const uint32_t*)(bhp + ks*32);
                uint32_t bh1 = *(const uint32_t*)(bhp + ks*32 + 16);
                uint32_t bl0 = *(const uint32_t*)(blp + ks*32);
                uint32_t bl1 = *(const uint32_t*)(blp + ks*32 + 16);
                mma16816(d, ah[ks], bh0, bh1);
                mma16816(d, al[ks], bh0, bh1);
                mma16816(d, ah[ks], bl0, bl1);
            }
            const int c = j*128 + n*8 + qd*2;
            int2   mv  = *(const int2*)&s_mask[c];
            float2 bi0 = *(const float2*)(bbp + (size_t)lr*TT + c);
            float2 bi1 = *(const float2*)(bbp + (size_t)(lr+8)*TT + c);
            float v00 = mv.x ? d.x + bi0.x : -1e9f;
            float v01 = mv.y ? d.y + bi0.y : -1e9f;
            float v10 = mv.x ? d.z + bi1.x : -1e9f;
            float v11 = mv.y ? d.w + bi1.y : -1e9f;
            *(float2*)(ab + (size_t)lr*TT + c)     = make_float2(v00, v01);
            *(float2*)(ab + (size_t)(lr+8)*TT + c) = make_float2(v10, v11);
            float nm0 = fmaxf(m0, fmaxf(v00, v01));
            s0 = s0*__expf(m0 - nm0) + __expf(v00 - nm0) + __expf(v01 - nm0);
            m0 = nm0;
            float nm1 = fmaxf(m1, fmaxf(v10, v11));
            s1 = s1*__expf(m1 - nm1) + __expf(v10 - nm1) + __expf(v11 - nm1);
            m1 = nm1;
        }
    }

    #pragma unroll
    for (int o = 1; o < 4; o <<= 1) {
        float mo = __shfl_xor_sync(0xffffffffu, m0, o);
        float so = __shfl_xor_sync(0xffffffffu, s0, o);
        float nm = fmaxf(m0, mo);
        s0 = s0*__expf(m0 - nm) + so*__expf(mo - nm); m0 = nm;
        mo = __shfl_xor_sync(0xffffffffu, m1, o);
        so = __shfl_xor_sync(0xffffffffu, s1, o);
        nm = fmaxf(m1, mo);
        s1 = s1*__expf(m1 - nm) + so*__expf(mo - nm); m1 = nm;
    }
    if (qd == 0) {
        const size_t gi = (size_t)(b*HH + h)*TT + q0;
        g_m[gi + lr]       = m0;  g_inv[gi + lr]     = 1.f/s0;
        g_m[gi + lr + 8]   = m1;  g_inv[gi + lr + 8] = 1.f/s1;
    }
}

// ==================== Kernel B: PV (HMMA bf16x3) — pipelined P loads ====================
#define PST 144
#define VSTB 144
#define B_PHI 0
#define B_PLO 18432
#define B_VHI 36864
#define B_VLO 46080
#define B_STAT 55296
#define B_TOTAL 56320

__global__ __launch_bounds__(256, 2)
void pv_mma(const float* __restrict__ gv, float* __restrict__ gattn,
            float* __restrict__ gout)
{
    extern __shared__ char sm[];
    char* s_phi = sm + B_PHI;
    char* s_plo = sm + B_PLO;
    char* s_vhi = sm + B_VHI;
    char* s_vlo = sm + B_VLO;
    float2* s_stat = (float2*)(sm + B_STAT);

    const int t = threadIdx.x, wid = t >> 5, lane = t & 31;
    const int h = blockIdx.y, b = blockIdx.z;
    const int q0 = blockIdx.x * 128;
    const int g = lane >> 2, qd = lane & 3;
    const int lr = wid*16 + g;

    const float* vb = gv + ((size_t)(b*HH + h))*TT*DD;
    float*       ab = gattn + (((size_t)(b*HH + h))*TT + q0)*TT;
    const size_t st = (size_t)(b*HH + h)*TT + q0;

    if (t < 128) s_stat[t] = make_float2(g_m[st + t], g_inv[st + t]);

    // P staging map: lanes 0-15 span a full row (float4 cols), lane bit4 = row of pair
    const int hl = lane >> 4;
    const int lc = (lane & 15) * 4;

    const int vkp = lane, vdq = wid;

    float4 o[8];
    #pragma unroll
    for (int i = 0; i < 8; ++i) o[i] = make_float4(0.f, 0.f, 0.f, 0.f);

    // prefetch raw P tile j=0 into registers
    float4 praw[8];
    #pragma unroll
    for (int rp = 0; rp < 8; ++rp) {
        const int r = wid*16 + rp*2 + hl;
        praw[rp] = *(const float4*)(ab + (size_t)r*TT + lc);
    }

    for (int j = 0; j < 32; ++j) {
        __syncthreads();   // prior MMA reads done; stats visible (j=0)
        // ---- convert phase: praw (already in regs) -> exp -> STG attn + smem hi/lo ----
        #pragma unroll
        for (int rp = 0; rp < 8; ++rp) {
            const int r = wid*16 + rp*2 + hl;
            const float2 ms = s_stat[r];
            float4 x = praw[rp];
            x.x = __expf(x.x - ms.x)*ms.y;
            x.y = __expf(x.y - ms.x)*ms.y;
            x.z = __expf(x.z - ms.x)*ms.y;
            x.w = __expf(x.w - ms.x)*ms.y;
            *(float4*)(ab + (size_t)r*TT + j*64 + lc) = x;
            uint32_t h0,l0,h1,l1;
            cvt_hilo2(x.x, x.y, h0, l0);
            cvt_hilo2(x.z, x.w, h1, l1);
            const int off = r*PST + lc*2;
            *(uint2*)(s_phi + off) = make_uint2(h0, h1);
            *(uint2*)(s_plo + off) = make_uint2(l0, l1);
        }
        // ---- stage V^T hi/lo (L2-resident; in-phase) ----
        {
            const float* v0 = vb + (size_t)(j*64 + 2*vkp)*DD + vdq*8;
            float4 a0 = *(const float4*)v0;
            float4 a1 = *(const float4*)(v0 + 4);
            float4 c0 = *(const float4*)(v0 + DD);
            float4 c1 = *(const float4*)(v0 + DD + 4);
            #pragma unroll
            for (int u = 0; u < 4; ++u) {
                float x = (u==0)?a0.x:(u==1)?a0.y:(u==2)?a0.z:a0.w;
                float y = (u==0)?c0.x:(u==1)?c0.y:(u==2)?c0.z:c0.w;
                uint32_t hp, lp;
                cvt_hilo2(x, y, hp, lp);
                const int off = (vdq*8 + u)*VSTB + vkp*4;
                *(uint32_t*)(s_vhi + off) = hp;
                *(uint32_t*)(s_vlo + off) = lp;
            }
            #pragma unroll
            for (int u = 0; u < 4; ++u) {
                float x = (u==0)?a1.x:(u==1)?a1.y:(u==2)?a1.z:a1.w;
                float y = (u==0)?c1.x:(u==1)?c1.y:(u==2)?c1.z:c1.w;
                uint32_t hp, lp;
                cvt_hilo2(x, y, hp, lp);
                const int off = (vdq*8 + 4 + u)*VSTB + vkp*4;
                *(uint32_t*)(s_vhi + off) = hp;
                *(uint32_t*)(s_vlo + off) = lp;
            }
        }
        __syncthreads();

        // ---- prefetch next raw P tile (LDGs fly during MMA phase) ----
        if (j + 1 < 32) {
            #pragma unroll
            for (int rp = 0; rp < 8; ++rp) {
                const int r = wid*16 + rp*2 + hl;
                praw[rp] = *(const float4*)(ab + (size_t)r*TT + (j+1)*64 + lc);
            }
        }

        // ---- MMA from smem ----
        #pragma unroll
        for (int kst = 0; kst < 4; ++kst) {
            const int abase = lr*PST + kst*32 + qd*4;
            uint32_t ph[4], pl[4];
            ph[0] = *(const uint32_t*)(s_phi + abase);
            ph[1] = *(const uint32_t*)(s_phi + abase + 8*PST);
            ph[2] = *(const uint32_t*)(s_phi + abase + 16);
            ph[3] = *(const uint32_t*)(s_phi + abase + 8*PST + 16);
            pl[0] = *(const uint32_t*)(s_plo + abase);
            pl[1] = *(const uint32_t*)(s_plo + abase + 8*PST);
            pl[2] = *(const uint32_t*)(s_plo + abase + 16);
            pl[3] = *(const uint32_t*)(s_plo + abase + 8*PST + 16);
            #pragma unroll
            for (int ns = 0; ns < 8; ++ns) {
                const int bbase = (ns*8 + g)*VSTB + kst*32 + qd*4;
                uint32_t bh0 = *(const uint32_t*)(s_vhi + bbase);
                uint32_t bh1 = *(const uint32_t*)(s_vhi + bbase + 16);
                uint32_t bl0 = *(const uint32_t*)(s_vlo + bbase);
                uint32_t bl1 = *(const uint32_t*)(s_vlo + bbase + 16);
                mma16816(o[ns], ph, bh0, bh1);
                mma16816(o[ns], pl, bh0, bh1);
                mma16816(o[ns], ph, bl0, bl1);
            }
        }
    }

    float* ob = gout + (((size_t)(b*HH + h))*TT + q0)*DD;
    #pragma unroll
    for (int ns = 0; ns < 8; ++ns) {
        const int c = ns*8 + qd*2;
        *(float2*)(ob + (size_t)lr*DD + c)     = make_float2(o[ns].x, o[ns].y);
        *(float2*)(ob + (size_t)(lr+8)*DD + c) = make_float2(o[ns].z, o[ns].w);
    }
}

extern "C" void kernel_launch(void* const* d_in, const int* in_sizes, int n_in,
                              void* d_out, int out_size)
{
    const float* q    = (const float*)d_in[0];
    const float* k    = (const float*)d_in[1];
    const float* v    = (const float*)d_in[2];
    const int*   mask = (const int*)d_in[3];
    const float* bias = (const float*)d_in[4];
    float* out  = (float*)d_out;
    float* attn = out + (long long)BB*HH*TT*DD;

    cudaFuncSetAttribute(qk_mma, cudaFuncAttributeMaxDynamicSharedMemorySize, A_TOTAL);
    cudaFuncSetAttribute(pv_mma, cudaFuncAttributeMaxDynamicSharedMemorySize, B_TOTAL);

    dim3 grid(TT/128, HH, BB);
    qk_mma<<<grid, 256, A_TOTAL>>>(q, k, mask, bias, attn);
    pv_mma<<<grid, 256, B_TOTAL>>>(v, attn, out);
}

// round 13
// speedup vs baseline: 2.1723x; 1.0140x over previous
#include <cuda_runtime.h>
#include <cuda_bf16.h>
#include <stdint.h>

#define TT 2048
#define DD 64
#define HH 16
#define BB 2

__device__ float g_m[BB*HH*TT];
__device__ float g_inv[BB*HH*TT];

__device__ __forceinline__ void mma16816(float4& d, const uint32_t* a,
                                         uint32_t b0, uint32_t b1) {
    asm volatile("mma.sync.aligned.m16n8k16.row.col.f32.bf16.bf16.f32 "
        "{%0,%1,%2,%3}, {%4,%5,%6,%7}, {%8,%9}, {%0,%1,%2,%3};"
        : "+f"(d.x), "+f"(d.y), "+f"(d.z), "+f"(d.w)
        : "r"(a[0]), "r"(a[1]), "r"(a[2]), "r"(a[3]), "r"(b0), "r"(b1));
}
__device__ __forceinline__ void cvt_hilo2(float x, float y, uint32_t& hi, uint32_t& lo) {
    __nv_bfloat162 hb = __floats2bfloat162_rn(x, y);
    __nv_bfloat162 lb = __floats2bfloat162_rn(x - __bfloat162float(hb.x),
                                              y - __bfloat162float(hb.y));
    hi = *reinterpret_cast<uint32_t*>(&hb);
    lo = *reinterpret_cast<uint32_t*>(&lb);
}

// ==================== Kernel A: QK^T (HMMA bf16x3) — pipelined K + bias ====================
#define A_KHI 0
#define A_KLO 18432
#define A_MASK 36864
#define A_TOTAL 45056

__global__ __launch_bounds__(256, 2)
void qk_mma(const float* __restrict__ gq, const float* __restrict__ gk,
            const int* __restrict__ gmask, const float* __restrict__ gbias,
            float* __restrict__ gattn)
{
    extern __shared__ char sm[];
    char* s_khi = sm + A_KHI;
    char* s_klo = sm + A_KLO;
    int*  s_mask = (int*)(sm + A_MASK);

    const int t = threadIdx.x, wid = t >> 5, lane = t & 31;
    const int h = blockIdx.y, b = blockIdx.z;
    const int q0 = blockIdx.x * 128;
    const int g = lane >> 2, qd = lane & 3;
    const int lr = wid*16 + g;

    const float* qb = gq + (((size_t)(b*HH + h))*TT + q0)*DD;
    const float* kb = gk + ((size_t)(b*HH + h))*TT*DD;
    const float* bbp = gbias + ((size_t)h*TT + q0)*TT;
    float*       ab = gattn + (((size_t)(b*HH + h))*TT + q0)*TT;

    ((int4*)s_mask)[t*2]   = ((const int4*)(gmask + b*TT))[t*2];
    ((int4*)s_mask)[t*2+1] = ((const int4*)(gmask + b*TT))[t*2+1];

    uint32_t ah[4][4], al[4][4];
    {
        const float* r0p = qb + (size_t)lr*DD;
        const float* r1p = qb + (size_t)(lr+8)*DD;
        #pragma unroll
        for (int ks = 0; ks < 4; ++ks) {
            const int c0 = ks*16 + qd*2;
            float2 x00 = *(const float2*)(r0p + c0);
            float2 x02 = *(const float2*)(r0p + c0 + 8);
            float2 x10 = *(const float2*)(r1p + c0);
            float2 x12 = *(const float2*)(r1p + c0 + 8);
            cvt_hilo2(x00.x*0.125f, x00.y*0.125f, ah[ks][0], al[ks][0]);
            cvt_hilo2(x10.x*0.125f, x10.y*0.125f, ah[ks][1], al[ks][1]);
            cvt_hilo2(x02.x*0.125f, x02.y*0.125f, ah[ks][2], al[ks][2]);
            cvt_hilo2(x12.x*0.125f, x12.y*0.125f, ah[ks][3], al[ks][3]);
        }
    }

    // K staging identity: thread owns key (t>>1), 32-col half (t&1)
    const int key = t >> 1, half = t & 1;
    const float* ksrc = kb + (size_t)key*DD + half*32;

    // prefetch K tile j=0 into registers
    float4 kraw[8];
    #pragma unroll
    for (int ch = 0; ch < 8; ++ch) kraw[ch] = ((const float4*)ksrc)[ch];

    float m0 = -3.4e38f, s0 = 0.f, m1 = -3.4e38f, s1 = 0.f;

    for (int j = 0; j < 16; ++j) {
        __syncthreads();   // prior MMA reads of smem done
        // ---- convert kraw (in regs) -> smem hi/lo ----
        #pragma unroll
        for (int ch = 0; ch < 4; ++ch) {
            float4 a = kraw[2*ch];
            float4 c = kraw[2*ch+1];
            uint32_t h0,l0,h1,l1,h2,l2,h3,l3;
            cvt_hilo2(a.x,a.y,h0,l0); cvt_hilo2(a.z,a.w,h1,l1);
            cvt_hilo2(c.x,c.y,h2,l2); cvt_hilo2(c.z,c.w,h3,l3);
            const int off = key*144 + half*64 + ch*16;
            *(uint4*)(s_khi + off) = make_uint4(h0,h1,h2,h3);
            *(uint4*)(s_klo + off) = make_uint4(l0,l1,l2,l3);
        }
        __syncthreads();

        // ---- prefetch next K tile (LDGs fly during MMA/epilogue) ----
        if (j + 1 < 16) {
            const float* nsrc = ksrc + (size_t)(j+1)*128*DD;
            #pragma unroll
            for (int ch = 0; ch < 8; ++ch) kraw[ch] = ((const float4*)nsrc)[ch];
        }

        // ---- MMA + epilogue, bias pipelined by one n ----
        float2 bi0 = *(const float2*)(bbp + (size_t)lr*TT + j*128 + qd*2);
        float2 bi1 = *(const float2*)(bbp + (size_t)(lr+8)*TT + j*128 + qd*2);

        #pragma unroll 2
        for (int n = 0; n < 16; ++n) {
            float2 nbi0, nbi1;
            if (n + 1 < 16) {
                const int cn = j*128 + (n+1)*8 + qd*2;
                nbi0 = *(const float2*)(bbp + (size_t)lr*TT + cn);
                nbi1 = *(const float2*)(bbp + (size_t)(lr+8)*TT + cn);
            }
            float4 d = make_float4(0.f, 0.f, 0.f, 0.f);
            const int keyl = n*8 + g;
            const char* bhp = s_khi + keyl*144 + qd*4;
            const char* blp = s_klo + keyl*144 + qd*4;
            #pragma unroll
            for (int ks = 0; ks < 4; ++ks) {
                uint32_t bh0 = *(const uint32_t*)(bhp + ks*32);
                uint32_t bh1 = *(const uint32_t*)(bhp + ks*32 + 16);
                uint32_t bl0 = *(const uint32_t*)(blp + ks*32);
                uint32_t bl1 = *(const uint32_t*)(blp + ks*32 + 16);
                mma16816(d, ah[ks], bh0, bh1);
                mma16816(d, al[ks], bh0, bh1);
                mma16816(d, ah[ks], bl0, bl1);
            }
            const int c = j*128 + n*8 + qd*2;
            int2 mv = *(const int2*)&s_mask[c];
            float v00 = mv.x ? d.x + bi0.x : -1e9f;
            float v01 = mv.y ? d.y + bi0.y : -1e9f;
            float v10 = mv.x ? d.z + bi1.x : -1e9f;
            float v11 = mv.y ? d.w + bi1.y : -1e9f;
            *(float2*)(ab + (size_t)lr*TT + c)     = make_float2(v00, v01);
            *(float2*)(ab + (size_t)(lr+8)*TT + c) = make_float2(v10, v11);
            float nm0 = fmaxf(m0, fmaxf(v00, v01));
            s0 = s0*__expf(m0 - nm0) + __expf(v00 - nm0) + __expf(v01 - nm0);
            m0 = nm0;
            float nm1 = fmaxf(m1, fmaxf(v10, v11));
            s1 = s1*__expf(m1 - nm1) + __expf(v10 - nm1) + __expf(v11 - nm1);
            m1 = nm1;
            bi0 = nbi0; bi1 = nbi1;
        }
    }

    #pragma unroll
    for (int o = 1; o < 4; o <<= 1) {
        float mo = __shfl_xor_sync(0xffffffffu, m0, o);
        float so = __shfl_xor_sync(0xffffffffu, s0, o);
        float nm = fmaxf(m0, mo);
        s0 = s0*__expf(m0 - nm) + so*__expf(mo - nm); m0 = nm;
        mo = __shfl_xor_sync(0xffffffffu, m1, o);
        so = __shfl_xor_sync(0xffffffffu, s1, o);
        nm = fmaxf(m1, mo);
        s1 = s1*__expf(m1 - nm) + so*__expf(mo - nm); m1 = nm;
    }
    if (qd == 0) {
        const size_t gi = (size_t)(b*HH + h)*TT + q0;
        g_m[gi + lr]       = m0;  g_inv[gi + lr]     = 1.f/s0;
        g_m[gi + lr + 8]   = m1;  g_inv[gi + lr + 8] = 1.f/s1;
    }
}

// ==================== Kernel B: PV (HMMA bf16x3) — unchanged from R12 (passing) ====================
#define PST 144
#define VSTB 144
#define B_PHI 0
#define B_PLO 18432
#define B_VHI 36864
#define B_VLO 46080
#define B_STAT 55296
#define B_TOTAL 56320

__global__ __launch_bounds__(256, 2)
void pv_mma(const float* __restrict__ gv, float* __restrict__ gattn,
            float* __restrict__ gout)
{
    extern __shared__ char sm[];
    char* s_phi = sm + B_PHI;
    char* s_plo = sm + B_PLO;
    char* s_vhi = sm + B_VHI;
    char* s_vlo = sm + B_VLO;
    float2* s_stat = (float2*)(sm + B_STAT);

    const int t = threadIdx.x, wid = t >> 5, lane = t & 31;
    const int h = blockIdx.y, b = blockIdx.z;
    const int q0 = blockIdx.x * 128;
    const int g = lane >> 2, qd = lane & 3;
    const int lr = wid*16 + g;

    const float* vb = gv + ((size_t)(b*HH + h))*TT*DD;
    float*       ab = gattn + (((size_t)(b*HH + h))*TT + q0)*TT;
    const size_t st = (size_t)(b*HH + h)*TT + q0;

    if (t < 128) s_stat[t] = make_float2(g_m[st + t], g_inv[st + t]);

    const int hl = lane >> 4;
    const int lc = (lane & 15) * 4;
    const int vkp = lane, vdq = wid;

    float4 o[8];
    #pragma unroll
    for (int i = 0; i < 8; ++i) o[i] = make_float4(0.f, 0.f, 0.f, 0.f);

    float4 praw[8];
    #pragma unroll
    for (int rp = 0; rp < 8; ++rp) {
        const int r = wid*16 + rp*2 + hl;
        praw[rp] = *(const float4*)(ab + (size_t)r*TT + lc);
    }

    for (int j = 0; j < 32; ++j) {
        __syncthreads();
        #pragma unroll
        for (int rp = 0; rp < 8; ++rp) {
            const int r = wid*16 + rp*2 + hl;
            const float2 ms = s_stat[r];
            float4 x = praw[rp];
            x.x = __expf(x.x - ms.x)*ms.y;
            x.y = __expf(x.y - ms.x)*ms.y;
            x.z = __expf(x.z - ms.x)*ms.y;
            x.w = __expf(x.w - ms.x)*ms.y;
            *(float4*)(ab + (size_t)r*TT + j*64 + lc) = x;
            uint32_t h0,l0,h1,l1;
            cvt_hilo2(x.x, x.y, h0, l0);
            cvt_hilo2(x.z, x.w, h1, l1);
            const int off = r*PST + lc*2;
            *(uint2*)(s_phi + off) = make_uint2(h0, h1);
            *(uint2*)(s_plo + off) = make_uint2(l0, l1);
        }
        {
            const float* v0 = vb + (size_t)(j*64 + 2*vkp)*DD + vdq*8;
            float4 a0 = *(const float4*)v0;
            float4 a1 = *(const float4*)(v0 + 4);
            float4 c0 = *(const float4*)(v0 + DD);
            float4 c1 = *(const float4*)(v0 + DD + 4);
            #pragma unroll
            for (int u = 0; u < 4; ++u) {
                float x = (u==0)?a0.x:(u==1)?a0.y:(u==2)?a0.z:a0.w;
                float y = (u==0)?c0.x:(u==1)?c0.y:(u==2)?c0.z:c0.w;
                uint32_t hp, lp;
                cvt_hilo2(x, y, hp, lp);
                const int off = (vdq*8 + u)*VSTB + vkp*4;
                *(uint32_t*)(s_vhi + off) = hp;
                *(uint32_t*)(s_vlo + off) = lp;
            }
            #pragma unroll
            for (int u = 0; u < 4; ++u) {
                float x = (u==0)?a1.x:(u==1)?a1.y:(u==2)?a1.z:a1.w;
                float y = (u==0)?c1.x:(u==1)?c1.y:(u==2)?c1.z:c1.w;
                uint32_t hp, lp;
                cvt_hilo2(x, y, hp, lp);
                const int off = (vdq*8 + 4 + u)*VSTB + vkp*4;
                *(uint32_t*)(s_vhi + off) = hp;
                *(uint32_t*)(s_vlo + off) = lp;
            }
        }
        __syncthreads();

        if (j + 1 < 32) {
            #pragma unroll
            for (int rp = 0; rp < 8; ++rp) {
                const int r = wid*16 + rp*2 + hl;
                praw[rp] = *(const float4*)(ab + (size_t)r*TT + (j+1)*64 + lc);
            }
        }

        #pragma unroll
        for (int kst = 0; kst < 4; ++kst) {
            const int abase = lr*PST + kst*32 + qd*4;
            uint32_t ph[4], pl[4];
            ph[0] = *(const uint32_t*)(s_phi + abase);
            ph[1] = *(const uint32_t*)(s_phi + abase + 8*PST);
            ph[2] = *(const uint32_t*)(s_phi + abase + 16);
            ph[3] = *(const uint32_t*)(s_phi + abase + 8*PST + 16);
            pl[0] = *(const uint32_t*)(s_plo + abase);
            pl[1] = *(const uint32_t*)(s_plo + abase + 8*PST);
            pl[2] = *(const uint32_t*)(s_plo + abase + 16);
            pl[3] = *(const uint32_t*)(s_plo + abase + 8*PST + 16);
            #pragma unroll
            for (int ns = 0; ns < 8; ++ns) {
                const int bbase = (ns*8 + g)*VSTB + kst*32 + qd*4;
                uint32_t bh0 = *(const uint32_t*)(s_vhi + bbase);
                uint32_t bh1 = *(const uint32_t*)(s_vhi + bbase + 16);
                uint32_t bl0 = *(const uint32_t*)(s_vlo + bbase);
                uint32_t bl1 = *(const uint32_t*)(s_vlo + bbase + 16);
                mma16816(o[ns], ph, bh0, bh1);
                mma16816(o[ns], pl, bh0, bh1);
                mma16816(o[ns], ph, bl0, bl1);
            }
        }
    }

    float* ob = gout + (((size_t)(b*HH + h))*TT + q0)*DD;
    #pragma unroll
    for (int ns = 0; ns < 8; ++ns) {
        const int c = ns*8 + qd*2;
        *(float2*)(ob + (size_t)lr*DD + c)     = make_float2(o[ns].x, o[ns].y);
        *(float2*)(ob + (size_t)(lr+8)*DD + c) = make_float2(o[ns].z, o[ns].w);
    }
}

extern "C" void kernel_launch(void* const* d_in, const int* in_sizes, int n_in,
                              void* d_out, int out_size)
{
    const float* q    = (const float*)d_in[0];
    const float* k    = (const float*)d_in[1];
    const float* v    = (const float*)d_in[2];
    const int*   mask = (const int*)d_in[3];
    const float* bias = (const float*)d_in[4];
    float* out  = (float*)d_out;
    float* attn = out + (long long)BB*HH*TT*DD;

    cudaFuncSetAttribute(qk_mma, cudaFuncAttributeMaxDynamicSharedMemorySize, A_TOTAL);
    cudaFuncSetAttribute(pv_mma, cudaFuncAttributeMaxDynamicSharedMemorySize, B_TOTAL);

    dim3 grid(TT/128, HH, BB);
    qk_mma<<<grid, 256, A_TOTAL>>>(q, k, mask, bias, attn);
    pv_mma<<<grid, 256, B_TOTAL>>>(v, attn, out);
}